// round 11
// baseline (speedup 1.0000x reference)
#include <cuda_runtime.h>
#include <cuda_bf16.h>
#include <math.h>
#include <stdint.h>

#define B 32
#define T 512
#define HID 512
#define VOCAB 4096
#define M_TOT (T * B)

// ---- recurrence tiling ----
#define NJT 16
#define NG  8
#define NREC (NJT * NG)          // 128 producer blocks
#define JW  32
#define GB  4
#define WS_STRIDE 516
#define SH_STRIDE 520

// ---- mma.sync projection GEMM config ----
#define PM 128
#define PN 128
#define PK 32
#define NCHUNK (HID / PK)        // 16
#define NMT (M_TOT / PM)         // 128 m tiles
#define NNT (VOCAB / PN)         // 32 n tiles
#define NPROJ (NMT * NNT)        // 4096 consumer blocks
#define ASTRIDE 40               // padded row (bf16) -> 80B, conflict-free ldmatrix
#define OFF_AHI 0
#define OFF_ALO 10240
#define OFF_BHI 20480
#define OFF_BLO 30720
#define STAGE_BYTES 40960
#define FUSED_SMEM (2 * STAGE_BYTES)   // 80 KB (>= recurrence's 78.5 KB)

__device__ float         g_Hall[M_TOT * HID];     // 32 MB fp32 hidden states
__device__ __nv_bfloat16 g_Ahi[M_TOT * HID];      // 16 MB
__device__ __nv_bfloat16 g_Alo[M_TOT * HID];      // 16 MB
__device__ __nv_bfloat16 g_Bhi[VOCAB * HID];      // 4 MB  (W_hq^T hi, K-major)
__device__ __nv_bfloat16 g_Blo[VOCAB * HID];      // 4 MB
__device__ unsigned g_cnt[NG];                    // monotonic per-group step counters

// ============================================================================
// helpers
// ============================================================================
__device__ __forceinline__ uint32_t smem_u32(const void* p) {
    uint32_t a;
    asm("{ .reg .u64 t; cvta.to.shared.u64 t, %1; cvt.u32.u64 %0, t; }"
        : "=r"(a) : "l"(p));
    return a;
}

__device__ __forceinline__ void cp16(uint32_t dst, const void* src) {
    asm volatile("cp.async.cg.shared.global [%0], [%1], 16;"
                 :: "r"(dst), "l"(src) : "memory");
}

template <int N>
__device__ __forceinline__ void cp_wait() {
    asm volatile("cp.async.wait_group %0;" :: "n"(N) : "memory");
}

__device__ __forceinline__ void ldsm4(uint32_t* r, uint32_t addr) {
    asm volatile("ldmatrix.sync.aligned.m8n8.x4.shared.b16 {%0,%1,%2,%3}, [%4];"
                 : "=r"(r[0]), "=r"(r[1]), "=r"(r[2]), "=r"(r[3]) : "r"(addr));
}

__device__ __forceinline__ void mma_bf16(float* c, const uint32_t* a, const uint32_t* b) {
    asm volatile(
        "mma.sync.aligned.m16n8k16.row.col.f32.bf16.bf16.f32 "
        "{%0,%1,%2,%3}, {%4,%5,%6,%7}, {%8,%9}, {%0,%1,%2,%3};"
        : "+f"(c[0]), "+f"(c[1]), "+f"(c[2]), "+f"(c[3])
        : "r"(a[0]), "r"(a[1]), "r"(a[2]), "r"(a[3]), "r"(b[0]), "r"(b[1]));
}

__device__ __forceinline__ unsigned ld_acq(const unsigned* p) {
    unsigned v;
    asm volatile("ld.global.acquire.gpu.u32 %0, [%1];" : "=r"(v) : "l"(p));
    return v;
}

// ============================================================================
// Projection tile loader (one K chunk of 32 into one stage buffer)
// ============================================================================
__device__ __forceinline__ void load_chunk(
    uint32_t dstbase, int tid, int c,
    const __nv_bfloat16* aH, const __nv_bfloat16* aL,
    const __nv_bfloat16* bH, const __nv_bfloat16* bL)
{
    const int r = tid >> 1;
    const int h = tid & 1;
    const uint32_t d = dstbase + (uint32_t)(r * 80 + h * 32);
    const size_t g = (size_t)r * HID + c * PK + h * 16;
    cp16(d + OFF_AHI,      aH + g);
    cp16(d + OFF_AHI + 16, aH + g + 8);
    cp16(d + OFF_ALO,      aL + g);
    cp16(d + OFF_ALO + 16, aL + g + 8);
    cp16(d + OFF_BHI,      bH + g);
    cp16(d + OFF_BHI + 16, bH + g + 8);
    cp16(d + OFF_BLO,      bL + g);
    cp16(d + OFF_BLO + 16, bL + g + 8);
    asm volatile("cp.async.commit_group;" ::: "memory");
}

// ============================================================================
// FUSED kernel: blocks 0..127 run the persistent recurrence (producers),
// blocks 128.. run projection tiles (consumers) gated on step counters.
// __launch_bounds__(256,2): 2 blocks/SM so every recurrence block co-resides
// with a projection block filling the idle tensor pipe.
// ============================================================================
__global__ void __launch_bounds__(256, 2) fused(
    const int* __restrict__ X,
    const float* __restrict__ state,
    const float* __restrict__ W_xh,
    const float* __restrict__ W_hh,
    const float* __restrict__ b_h,
    const float* __restrict__ bq,
    float* __restrict__ C)
{
    extern __shared__ char smraw[];
    const int bid = blockIdx.x;
    const int tid = threadIdx.x;

    if (bid < NREC) {
        // ====================== RECURRENCE PRODUCER ======================
        float* smem = (float*)smraw;
        float* Ws   = smem;
        float* sH   = Ws + JW * WS_STRIDE;
        float* sRed = sH + GB * SH_STRIDE;

        const int jt  = bid & 15;
        const int grp = bid >> 4;
        const int j0  = jt * JW;
        const int b0  = grp * GB;

        {   // preload W_hh slice once (transposed into SMEM)
            const int lane8 = tid & 7;
            const int kk    = tid >> 3;
            for (int kb = 0; kb < HID; kb += 32) {
                const int k = kb + kk;
                float4 v = *reinterpret_cast<const float4*>(&W_hh[(size_t)k * HID + j0 + lane8 * 4]);
                Ws[(lane8 * 4 + 0) * WS_STRIDE + k] = v.x;
                Ws[(lane8 * 4 + 1) * WS_STRIDE + k] = v.y;
                Ws[(lane8 * 4 + 2) * WS_STRIDE + k] = v.z;
                Ws[(lane8 * 4 + 3) * WS_STRIDE + k] = v.w;
            }
        }

        const int jq = tid & 7;
        const int bb = (tid >> 3) & 3;
        const int ks = tid >> 5;
        const int kbase = ks * 64;

        int fb = -1, fj = -1;
        float bh_reg = 0.f;
        const int* xrow = 0;
        if (tid < 128) {
            fb = b0 + (tid >> 5);
            fj = j0 + (tid & 31);
            bh_reg = __ldg(&b_h[fj]);
            xrow = X + fb * T;
        }

        __syncthreads();

        for (int t = 0; t < T; t++) {
            float eb = 0.f;
            if (tid < 128) {
                const int tok = __ldg(&xrow[t]);
                eb = __ldg(&W_xh[(size_t)tok * HID + fj]) + bh_reg;
            }

            const float* Hprev = (t == 0) ? state : (g_Hall + (size_t)(t - 1) * B * HID);
            for (int i = tid; i < GB * (HID / 4); i += 256) {
                const int bi  = i >> 7;
                const int kk4 = i & 127;
                float4 v = reinterpret_cast<const float4*>(&Hprev[(size_t)(b0 + bi) * HID])[kk4];
                *reinterpret_cast<float4*>(&sH[bi * SH_STRIDE + kk4 * 4]) = v;
            }
            __syncthreads();

            float acc0 = 0.f, acc1 = 0.f, acc2 = 0.f, acc3 = 0.f;
            const float* hrow = &sH[bb * SH_STRIDE + kbase];
            const float* w0 = &Ws[(jq +  0) * WS_STRIDE + kbase];
            const float* w1 = &Ws[(jq +  8) * WS_STRIDE + kbase];
            const float* w2 = &Ws[(jq + 16) * WS_STRIDE + kbase];
            const float* w3 = &Ws[(jq + 24) * WS_STRIDE + kbase];
            #pragma unroll
            for (int kk = 0; kk < 64; kk += 4) {
                const float4 h = *reinterpret_cast<const float4*>(&hrow[kk]);
                const float4 a = *reinterpret_cast<const float4*>(&w0[kk]);
                const float4 b = *reinterpret_cast<const float4*>(&w1[kk]);
                const float4 c = *reinterpret_cast<const float4*>(&w2[kk]);
                const float4 d = *reinterpret_cast<const float4*>(&w3[kk]);
                acc0 += a.x * h.x + a.y * h.y + a.z * h.z + a.w * h.w;
                acc1 += b.x * h.x + b.y * h.y + b.z * h.z + b.w * h.w;
                acc2 += c.x * h.x + c.y * h.y + c.z * h.z + c.w * h.w;
                acc3 += d.x * h.x + d.y * h.y + d.z * h.z + d.w * h.w;
            }
            sRed[ks * 128 + bb * 32 + jq +  0] = acc0;
            sRed[ks * 128 + bb * 32 + jq +  8] = acc1;
            sRed[ks * 128 + bb * 32 + jq + 16] = acc2;
            sRed[ks * 128 + bb * 32 + jq + 24] = acc3;
            __syncthreads();

            if (tid < 128) {
                float s = 0.f;
                #pragma unroll
                for (int q = 0; q < 8; q++) s += sRed[q * 128 + tid];
                s += eb;
                const float h = tanhf(s);
                const size_t ridx = ((size_t)t * B + fb) * HID + fj;
                g_Hall[ridx] = h;
                const __nv_bfloat16 hi = __float2bfloat16(h);
                g_Ahi[ridx] = hi;
                g_Alo[ridx] = __float2bfloat16(h - __bfloat162float(hi));
            }
            __syncthreads();

            if (tid == 0) {
                asm volatile("red.release.gpu.global.add.u32 [%0], %1;"
                             :: "l"(&g_cnt[grp]), "r"(1u) : "memory");
                const unsigned target = (unsigned)(NJT * (t + 1));
                while (ld_acq(&g_cnt[grp]) < target) { }
            }
            __syncthreads();
        }
        // NOTE: no counter reset here — consumers may still be polling.
        // Reset happens in the trailing cleanup kernel.
    } else {
        // ====================== PROJECTION CONSUMER ======================
        const int pid   = bid - NREC;
        const int mtile = pid >> 5;          // ascending with bid -> earliest data first
        const int ntile = pid & 31;
        const int bm = mtile * PM;
        const int bn = ntile * PN;

        // wait until timesteps [4*mtile, 4*mtile+4) are complete in ALL groups
        {
            const unsigned target = (unsigned)(NJT * (4 * mtile + 4));
            if (tid < NG) {
                while (ld_acq(&g_cnt[tid]) < target) {
                    __nanosleep(256);
                }
            }
            __syncthreads();
        }

        const uint32_t sb = smem_u32(smraw);
        const int lane = tid & 31;
        const int wid  = tid >> 5;
        const int wm   = wid & 1;
        const int wn   = wid >> 1;

        const __nv_bfloat16* aH = g_Ahi + (size_t)bm * HID;
        const __nv_bfloat16* aL = g_Alo + (size_t)bm * HID;
        const __nv_bfloat16* bH = g_Bhi + (size_t)bn * HID;
        const __nv_bfloat16* bL = g_Blo + (size_t)bn * HID;

        float acc[4][4][4];
        #pragma unroll
        for (int i = 0; i < 4; i++)
            #pragma unroll
            for (int j = 0; j < 4; j++)
                #pragma unroll
                for (int q = 0; q < 4; q++) acc[i][j][q] = 0.f;

        const uint32_t a_off = (uint32_t)(((wm * 64 + (lane & 15)) * ASTRIDE
                                           + ((lane >> 4) << 3)) * 2);
        const uint32_t b_off = (uint32_t)(((wn * 32 + (lane & 7) + (((lane >> 4) & 1) << 3)) * ASTRIDE
                                           + (((lane >> 3) & 1) << 3)) * 2);

        load_chunk(sb, tid, 0, aH, aL, bH, bL);

        for (int c = 0; c < NCHUNK; c++) {
            if (c + 1 < NCHUNK) {
                load_chunk(sb + (uint32_t)((c + 1) & 1) * STAGE_BYTES, tid, c + 1,
                           aH, aL, bH, bL);
                cp_wait<1>();
            } else {
                cp_wait<0>();
            }
            __syncthreads();

            const uint32_t stage = sb + (uint32_t)(c & 1) * STAGE_BYTES;
            #pragma unroll
            for (int ksi = 0; ksi < 2; ksi++) {
                const uint32_t kadd = (uint32_t)(ksi * 32);
                uint32_t bh2[2][4], bl2[2][4];
                #pragma unroll
                for (int nf2 = 0; nf2 < 2; nf2++) {
                    const uint32_t o = stage + b_off + kadd + (uint32_t)(nf2 * 16 * ASTRIDE * 2);
                    ldsm4(bh2[nf2], o + OFF_BHI);
                    ldsm4(bl2[nf2], o + OFF_BLO);
                }
                #pragma unroll
                for (int mf = 0; mf < 4; mf++) {
                    uint32_t ah[4], al[4];
                    const uint32_t o = stage + a_off + kadd + (uint32_t)(mf * 16 * ASTRIDE * 2);
                    ldsm4(ah, o + OFF_AHI);
                    ldsm4(al, o + OFF_ALO);
                    #pragma unroll
                    for (int nf = 0; nf < 4; nf++) {
                        const uint32_t* bhp = &bh2[nf >> 1][(nf & 1) * 2];
                        const uint32_t* blp = &bl2[nf >> 1][(nf & 1) * 2];
                        mma_bf16(acc[mf][nf], ah, bhp);   // hi*hi
                        mma_bf16(acc[mf][nf], al, bhp);   // lo*hi
                        mma_bf16(acc[mf][nf], ah, blp);   // hi*lo
                    }
                }
            }
            __syncthreads();
        }

        // epilogue: direct stores with bias
        #pragma unroll
        for (int mf = 0; mf < 4; mf++) {
            const int row0 = bm + wm * 64 + mf * 16 + (lane >> 2);
            #pragma unroll
            for (int nf = 0; nf < 4; nf++) {
                const int col = bn + wn * 32 + nf * 8 + ((lane & 3) << 1);
                const float2 bias = *reinterpret_cast<const float2*>(bq + col);
                float2 v0, v1;
                v0.x = acc[mf][nf][0] + bias.x;
                v0.y = acc[mf][nf][1] + bias.y;
                v1.x = acc[mf][nf][2] + bias.x;
                v1.y = acc[mf][nf][3] + bias.y;
                *reinterpret_cast<float2*>(&C[(size_t)row0 * VOCAB + col]) = v0;
                *reinterpret_cast<float2*>(&C[(size_t)(row0 + 8) * VOCAB + col]) = v1;
            }
        }
    }
}

// ============================================================================
// Prep: transpose + split W_hq (HID, VOCAB) -> Bhi/Blo (VOCAB, HID) bf16
// ============================================================================
__global__ void __launch_bounds__(256) prep_b(const float* __restrict__ Wq)
{
    __shared__ float tl[32][33];
    const int n0 = blockIdx.x * 32;
    const int k0 = blockIdx.y * 32;
    const int tx = threadIdx.x;
    const int ty = threadIdx.y;

    #pragma unroll
    for (int i = 0; i < 32; i += 8)
        tl[ty + i][tx] = Wq[(size_t)(k0 + ty + i) * VOCAB + n0 + tx];
    __syncthreads();

    #pragma unroll
    for (int i = 0; i < 32; i += 8) {
        const float v = tl[tx][ty + i];
        const size_t o = (size_t)(n0 + ty + i) * HID + k0 + tx;
        const __nv_bfloat16 hi = __float2bfloat16(v);
        g_Bhi[o] = hi;
        g_Blo[o] = __float2bfloat16(v - __bfloat162float(hi));
    }
}

// ============================================================================
// Cleanup: reset counters for the next graph replay (runs after fused)
// ============================================================================
__global__ void cleanup_counters()
{
    if (threadIdx.x < NG) g_cnt[threadIdx.x] = 0;
    __threadfence();
}

__global__ void copy_hfinal(float* __restrict__ out)
{
    int i = blockIdx.x * 256 + threadIdx.x;
    if (i < B * HID)
        out[i] = g_Hall[(size_t)(T - 1) * B * HID + i];
}

// ============================================================================
extern "C" void kernel_launch(void* const* d_in, const int* in_sizes, int n_in,
                              void* d_out, int out_size)
{
    const int*   X     = (const int*)d_in[0];
    const float* state = (const float*)d_in[1];
    const float* W_xh  = (const float*)d_in[2];
    const float* W_hh  = (const float*)d_in[3];
    const float* b_h   = (const float*)d_in[4];
    const float* W_hq  = (const float*)d_in[5];
    const float* b_q   = (const float*)d_in[6];
    float* out = (float*)d_out;

    // 0) split/transpose W_hq -> bf16 hi/lo (completes before fused starts)
    prep_b<<<dim3(VOCAB / 32, HID / 32), dim3(32, 8)>>>(W_hq);

    // 1) fused producer/consumer: recurrence blocks + projection blocks
    cudaFuncSetAttribute(fused, cudaFuncAttributeMaxDynamicSharedMemorySize, FUSED_SMEM);
    fused<<<NREC + NPROJ, 256, FUSED_SMEM>>>(X, state, W_xh, W_hh, b_h, b_q, out);

    // 2) reset counters for next replay
    cleanup_counters<<<1, 32>>>();

    // 3) optional H_final tail
    if (out_size >= M_TOT * VOCAB + B * HID) {
        copy_hfinal<<<(B * HID + 255) / 256, 256>>>(out + (size_t)M_TOT * VOCAB);
    }
}

// round 12
// speedup vs baseline: 1.1811x; 1.1811x over previous
#include <cuda_runtime.h>
#include <cuda_bf16.h>
#include <math.h>
#include <stdint.h>

#define B 32
#define T 512
#define HID 512
#define VOCAB 4096
#define M_TOT (T * B)

// ---- recurrence tiling ----
#define NJT 16
#define NG  8
#define JW  32
#define GB  4
#define WS_STRIDE 516
#define SH_STRIDE 520

// ---- bulk-pipeline projection GEMM config ----
#define PM 256                   // CTA rows (2 blocks of 128)
#define PN 128                   // CTA cols (1 ntile block)
#define KC 64                    // k per chunk
#define NCHUNK (HID / KC)        // 8
#define BLK_ELEMS 8192           // 128x64 bf16 = 16KB block
#define PROJ_STAGE 98304u        // 96KB per stage (Ahi 32K | Alo 32K | Bhi 16K | Blo 16K)
#define POFF_ALO 32768u
#define POFF_BHI 65536u
#define POFF_BLO 81920u
#define PROJ_SMEM (2 * 98304 + 32)

__device__ float         g_Hall[M_TOT * HID];     // fp32 hidden states
__device__ __nv_bfloat16 g_Ahi[M_TOT * HID];      // chunk-major swizzled blocks
__device__ __nv_bfloat16 g_Alo[M_TOT * HID];
__device__ __nv_bfloat16 g_Bhi[VOCAB * HID];      // chunk-major swizzled blocks
__device__ __nv_bfloat16 g_Blo[VOCAB * HID];
__device__ unsigned g_cnt[NG];
__device__ unsigned g_exit[NG];

// ============================================================================
// helpers
// ============================================================================
__device__ __forceinline__ uint32_t smem_u32(const void* p) {
    uint32_t a;
    asm("{ .reg .u64 t; cvta.to.shared.u64 t, %1; cvt.u32.u64 %0, t; }"
        : "=r"(a) : "l"(p));
    return a;
}

__device__ __forceinline__ void mbar_init(uint32_t a, uint32_t cnt) {
    asm volatile("mbarrier.init.shared.b64 [%0], %1;" :: "r"(a), "r"(cnt) : "memory");
}

__device__ __forceinline__ void mbar_expect_tx(uint32_t a, uint32_t bytes) {
    asm volatile("mbarrier.arrive.expect_tx.shared.b64 _, [%0], %1;"
                 :: "r"(a), "r"(bytes) : "memory");
}

__device__ __forceinline__ void mbar_wait(uint32_t addr, uint32_t parity) {
    asm volatile(
        "{\n\t.reg .pred P;\n"
        "WAITLP_%=:\n\t"
        "mbarrier.try_wait.parity.acquire.cta.shared::cta.b64 P, [%0], %1, 0x989680;\n\t"
        "@P bra.uni WAITDN_%=;\n\t"
        "bra.uni WAITLP_%=;\n"
        "WAITDN_%=:\n\t}"
        :: "r"(addr), "r"(parity) : "memory");
}

__device__ __forceinline__ void bulk_cp(uint32_t dst, const void* src,
                                        uint32_t bytes, uint32_t mbar) {
    asm volatile(
        "cp.async.bulk.shared::cluster.global.mbarrier::complete_tx::bytes "
        "[%0], [%1], %2, [%3];"
        :: "r"(dst), "l"(src), "r"(bytes), "r"(mbar) : "memory");
}

__device__ __forceinline__ void ldsm4(uint32_t* r, uint32_t addr) {
    asm volatile("ldmatrix.sync.aligned.m8n8.x4.shared.b16 {%0,%1,%2,%3}, [%4];"
                 : "=r"(r[0]), "=r"(r[1]), "=r"(r[2]), "=r"(r[3]) : "r"(addr));
}

__device__ __forceinline__ void mma_bf16(float* c, const uint32_t* a, const uint32_t* b) {
    asm volatile(
        "mma.sync.aligned.m16n8k16.row.col.f32.bf16.bf16.f32 "
        "{%0,%1,%2,%3}, {%4,%5,%6,%7}, {%8,%9}, {%0,%1,%2,%3};"
        : "+f"(c[0]), "+f"(c[1]), "+f"(c[2]), "+f"(c[3])
        : "r"(a[0]), "r"(a[1]), "r"(a[2]), "r"(a[3]), "r"(b[0]), "r"(b[1]));
}

__device__ __forceinline__ unsigned ld_acq(const unsigned* p) {
    unsigned v;
    asm volatile("ld.global.acquire.gpu.u32 %0, [%1];" : "=r"(v) : "l"(p));
    return v;
}

// swizzled element index inside a 128x64 block (units: bf16 elems)
__device__ __forceinline__ int swz_idx(int row, int col) {
    return (row << 6) + (((col >> 3) ^ (row & 7)) << 3) + (col & 7);
}

// ============================================================================
// Persistent recurrence: 512 steps, per-group software barrier.
// Emits H fp32 (g_Hall) + bf16 hi/lo in chunk-major swizzled blocks.
// ============================================================================
__global__ void __launch_bounds__(256) rnn_persist(
    const int* __restrict__ X,
    const float* __restrict__ state,
    const float* __restrict__ W_xh,
    const float* __restrict__ W_hh,
    const float* __restrict__ b_h)
{
    extern __shared__ float smem[];
    float* Ws   = smem;
    float* sH   = Ws + JW * WS_STRIDE;
    float* sRed = sH + GB * SH_STRIDE;

    const int tid = threadIdx.x;
    const int jt  = blockIdx.x;
    const int grp = blockIdx.y;
    const int j0  = jt * JW;
    const int b0  = grp * GB;

    {   // preload W_hh slice once (transposed into SMEM)
        const int lane8 = tid & 7;
        const int kk    = tid >> 3;
        for (int kb = 0; kb < HID; kb += 32) {
            const int k = kb + kk;
            float4 v = *reinterpret_cast<const float4*>(&W_hh[(size_t)k * HID + j0 + lane8 * 4]);
            Ws[(lane8 * 4 + 0) * WS_STRIDE + k] = v.x;
            Ws[(lane8 * 4 + 1) * WS_STRIDE + k] = v.y;
            Ws[(lane8 * 4 + 2) * WS_STRIDE + k] = v.z;
            Ws[(lane8 * 4 + 3) * WS_STRIDE + k] = v.w;
        }
    }

    const int jq = tid & 7;
    const int bb = (tid >> 3) & 3;
    const int ks = tid >> 5;
    const int kbase = ks * 64;

    int fb = -1, fj = -1;
    float bh_reg = 0.f;
    const int* xrow = 0;
    int fkc = 0, fcol = 0;
    if (tid < 128) {
        fb = b0 + (tid >> 5);
        fj = j0 + (tid & 31);
        bh_reg = __ldg(&b_h[fj]);
        xrow = X + fb * T;
        fkc  = fj >> 6;
        fcol = fj & 63;
    }

    __syncthreads();

    for (int t = 0; t < T; t++) {
        float eb = 0.f;
        if (tid < 128) {
            const int tok = __ldg(&xrow[t]);
            eb = __ldg(&W_xh[(size_t)tok * HID + fj]) + bh_reg;
        }

        const float* Hprev = (t == 0) ? state : (g_Hall + (size_t)(t - 1) * B * HID);
        for (int i = tid; i < GB * (HID / 4); i += 256) {
            const int bi  = i >> 7;
            const int kk4 = i & 127;
            float4 v = reinterpret_cast<const float4*>(&Hprev[(size_t)(b0 + bi) * HID])[kk4];
            *reinterpret_cast<float4*>(&sH[bi * SH_STRIDE + kk4 * 4]) = v;
        }
        __syncthreads();

        float acc0 = 0.f, acc1 = 0.f, acc2 = 0.f, acc3 = 0.f;
        const float* hrow = &sH[bb * SH_STRIDE + kbase];
        const float* w0 = &Ws[(jq +  0) * WS_STRIDE + kbase];
        const float* w1 = &Ws[(jq +  8) * WS_STRIDE + kbase];
        const float* w2 = &Ws[(jq + 16) * WS_STRIDE + kbase];
        const float* w3 = &Ws[(jq + 24) * WS_STRIDE + kbase];
        #pragma unroll
        for (int kk = 0; kk < 64; kk += 4) {
            const float4 h = *reinterpret_cast<const float4*>(&hrow[kk]);
            const float4 a = *reinterpret_cast<const float4*>(&w0[kk]);
            const float4 b = *reinterpret_cast<const float4*>(&w1[kk]);
            const float4 c = *reinterpret_cast<const float4*>(&w2[kk]);
            const float4 d = *reinterpret_cast<const float4*>(&w3[kk]);
            acc0 += a.x * h.x + a.y * h.y + a.z * h.z + a.w * h.w;
            acc1 += b.x * h.x + b.y * h.y + b.z * h.z + b.w * h.w;
            acc2 += c.x * h.x + c.y * h.y + c.z * h.z + c.w * h.w;
            acc3 += d.x * h.x + d.y * h.y + d.z * h.z + d.w * h.w;
        }
        sRed[ks * 128 + bb * 32 + jq +  0] = acc0;
        sRed[ks * 128 + bb * 32 + jq +  8] = acc1;
        sRed[ks * 128 + bb * 32 + jq + 16] = acc2;
        sRed[ks * 128 + bb * 32 + jq + 24] = acc3;
        __syncthreads();

        if (tid < 128) {
            float s = 0.f;
            #pragma unroll
            for (int q = 0; q < 8; q++) s += sRed[q * 128 + tid];
            s += eb;
            const float h = tanhf(s);
            const int m = t * B + fb;
            g_Hall[(size_t)m * HID + fj] = h;
            const __nv_bfloat16 hi = __float2bfloat16(h);
            const __nv_bfloat16 lo = __float2bfloat16(h - __bfloat162float(hi));
            // chunk-major swizzled block store
            const int idx = (((m >> 7) * NCHUNK + fkc) << 13)
                          + swz_idx(m & 127, fcol);
            g_Ahi[idx] = hi;
            g_Alo[idx] = lo;
        }
        __syncthreads();

        if (tid == 0) {
            asm volatile("red.release.gpu.global.add.u32 [%0], %1;"
                         :: "l"(&g_cnt[grp]), "r"(1u) : "memory");
            const unsigned target = (unsigned)(NJT * (t + 1));
            while (ld_acq(&g_cnt[grp]) < target) { }
        }
        __syncthreads();
    }

    // reset barrier state for next graph replay
    if (tid == 0) {
        const unsigned v = atomicAdd(&g_exit[grp], 1u);
        if (v == NJT - 1) {
            g_cnt[grp]  = 0;
            g_exit[grp] = 0;
            __threadfence();
        }
    }
}

// ============================================================================
// Prep: transpose + split W_hq (HID, VOCAB) -> chunk-major swizzled Bhi/Blo
// ============================================================================
__global__ void __launch_bounds__(256) prep_b(const float* __restrict__ Wq)
{
    __shared__ float tl[32][33];
    const int n0 = blockIdx.x * 32;
    const int k0 = blockIdx.y * 32;
    const int tx = threadIdx.x;
    const int ty = threadIdx.y;

    #pragma unroll
    for (int i = 0; i < 32; i += 8)
        tl[ty + i][tx] = Wq[(size_t)(k0 + ty + i) * VOCAB + n0 + tx];
    __syncthreads();

    #pragma unroll
    for (int i = 0; i < 32; i += 8) {
        const float v = tl[tx][ty + i];      // Wq[k0+tx][n0+ty+i]
        const int n = n0 + ty + i;
        const int k = k0 + tx;
        const int idx = (((n >> 7) * NCHUNK + (k >> 6)) << 13)
                      + swz_idx(n & 127, k & 63);
        const __nv_bfloat16 hi = __float2bfloat16(v);
        g_Bhi[idx] = hi;
        g_Blo[idx] = __float2bfloat16(v - __bfloat162float(hi));
    }
}

// ============================================================================
// Bulk-pipelined projection GEMM: C = Hall @ W_hq + bq (3-pass bf16 split)
// CTA 256x128, 512 threads (16 warps, 4m x 4n of 64x32), K-chunk 64,
// 2-stage cp.async.bulk + mbarrier pipeline, pre-swizzled smem tiles.
// ============================================================================
__device__ __forceinline__ void issue_chunk(uint32_t stage, uint32_t mbar,
                                            int c, int by, int bx)
{
    mbar_expect_tx(mbar, PROJ_STAGE);
    const size_t a0 = (size_t)((2 * by) * NCHUNK + c) * BLK_ELEMS;
    const size_t a1 = (size_t)((2 * by + 1) * NCHUNK + c) * BLK_ELEMS;
    const size_t b0 = (size_t)(bx * NCHUNK + c) * BLK_ELEMS;
    bulk_cp(stage,             g_Ahi + a0, 16384, mbar);
    bulk_cp(stage + 16384u,    g_Ahi + a1, 16384, mbar);
    bulk_cp(stage + POFF_ALO,          g_Alo + a0, 16384, mbar);
    bulk_cp(stage + POFF_ALO + 16384u, g_Alo + a1, 16384, mbar);
    bulk_cp(stage + POFF_BHI,  g_Bhi + b0, 16384, mbar);
    bulk_cp(stage + POFF_BLO,  g_Blo + b0, 16384, mbar);
}

__global__ void __launch_bounds__(512, 1) proj_bulk(
    const float* __restrict__ bq,
    float* __restrict__ C)
{
    extern __shared__ char smc[];
    const uint32_t sb  = smem_u32(smc);
    const uint32_t mb0 = sb + 2 * PROJ_STAGE;
    const uint32_t mb1 = mb0 + 8;

    const int tid  = threadIdx.x;
    const int lane = tid & 31;
    const int wid  = tid >> 5;
    const int wm   = wid & 3;       // 4 m-quarters of 64
    const int wn   = wid >> 2;      // 4 n-quarters of 32
    const int bx = blockIdx.x, by = blockIdx.y;
    const int bm = by * PM;
    const int bn = bx * PN;

    if (tid == 0) { mbar_init(mb0, 1); mbar_init(mb1, 1); }
    __syncthreads();

    if (tid == 0) {
        issue_chunk(sb,              mb0, 0, by, bx);
        issue_chunk(sb + PROJ_STAGE, mb1, 1, by, bx);
    }

    float acc[4][4][4];
    #pragma unroll
    for (int i = 0; i < 4; i++)
        #pragma unroll
        for (int j = 0; j < 4; j++)
            #pragma unroll
            for (int q = 0; q < 4; q++) acc[i][j][q] = 0.f;

    // per-lane fragment geometry (swizzle-aware)
    const int rA = wm * 64 + (lane & 15);                       // + mf*16 later
    const uint32_t cuA = (uint32_t)(lane >> 4);
    const uint32_t eA  = (uint32_t)(rA & 7);
    const int rB = wn * 32 + (lane & 7) + (((lane >> 4) & 1) << 3);  // + nf2*16 later
    const uint32_t cuB = (uint32_t)((lane >> 3) & 1);
    const uint32_t eB  = (uint32_t)(rB & 7);

    for (int c = 0; c < NCHUNK; c++) {
        mbar_wait((c & 1) ? mb1 : mb0, (uint32_t)((c >> 1) & 1));
        const uint32_t S = sb + (uint32_t)(c & 1) * PROJ_STAGE;

        #pragma unroll
        for (int ksi = 0; ksi < 4; ksi++) {
            uint32_t bh2[2][4], bl2[2][4];
            #pragma unroll
            for (int nf2 = 0; nf2 < 2; nf2++) {
                const uint32_t addr = S + POFF_BHI
                    + (uint32_t)(rB * 128 + nf2 * 2048)
                    + (((((uint32_t)ksi << 1) | cuB) ^ eB) << 4);
                ldsm4(bh2[nf2], addr);
                ldsm4(bl2[nf2], addr + (POFF_BLO - POFF_BHI));
            }
            #pragma unroll
            for (int mf = 0; mf < 4; mf++) {
                uint32_t ah[4], al[4];
                const uint32_t addr = S
                    + (uint32_t)(rA * 128 + mf * 2048)
                    + (((((uint32_t)ksi << 1) | cuA) ^ eA) << 4);
                ldsm4(ah, addr);
                ldsm4(al, addr + POFF_ALO);
                #pragma unroll
                for (int nf = 0; nf < 4; nf++) {
                    const uint32_t* bhp = &bh2[nf >> 1][(nf & 1) * 2];
                    const uint32_t* blp = &bl2[nf >> 1][(nf & 1) * 2];
                    mma_bf16(acc[mf][nf], ah, bhp);   // hi*hi
                    mma_bf16(acc[mf][nf], al, bhp);   // lo*hi
                    mma_bf16(acc[mf][nf], ah, blp);   // hi*lo
                }
            }
        }
        __syncthreads();
        if (tid == 0 && c < NCHUNK - 2) {
            issue_chunk(S, (c & 1) ? mb1 : mb0, c + 2, by, bx);
        }
    }

    // epilogue: direct stores with bias
    #pragma unroll
    for (int mf = 0; mf < 4; mf++) {
        const int row0 = bm + wm * 64 + mf * 16 + (lane >> 2);
        #pragma unroll
        for (int nf = 0; nf < 4; nf++) {
            const int col = bn + wn * 32 + nf * 8 + ((lane & 3) << 1);
            const float2 bias = *reinterpret_cast<const float2*>(bq + col);
            float2 v0, v1;
            v0.x = acc[mf][nf][0] + bias.x;
            v0.y = acc[mf][nf][1] + bias.y;
            v1.x = acc[mf][nf][2] + bias.x;
            v1.y = acc[mf][nf][3] + bias.y;
            *reinterpret_cast<float2*>(&C[(size_t)row0 * VOCAB + col]) = v0;
            *reinterpret_cast<float2*>(&C[(size_t)(row0 + 8) * VOCAB + col]) = v1;
        }
    }
}

__global__ void copy_hfinal(float* __restrict__ out)
{
    int i = blockIdx.x * 256 + threadIdx.x;
    if (i < B * HID)
        out[i] = g_Hall[(size_t)(T - 1) * B * HID + i];
}

// ============================================================================
extern "C" void kernel_launch(void* const* d_in, const int* in_sizes, int n_in,
                              void* d_out, int out_size)
{
    const int*   X     = (const int*)d_in[0];
    const float* state = (const float*)d_in[1];
    const float* W_xh  = (const float*)d_in[2];
    const float* W_hh  = (const float*)d_in[3];
    const float* b_h   = (const float*)d_in[4];
    const float* W_hq  = (const float*)d_in[5];
    const float* b_q   = (const float*)d_in[6];
    float* out = (float*)d_out;

    // 0) split/transpose W_hq -> chunk-major swizzled bf16 hi/lo
    prep_b<<<dim3(VOCAB / 32, HID / 32), dim3(32, 8)>>>(W_hq);

    // 1) persistent recurrence
    const int rec_smem = (JW * WS_STRIDE + GB * SH_STRIDE + 8 * 128) * (int)sizeof(float);
    cudaFuncSetAttribute(rnn_persist, cudaFuncAttributeMaxDynamicSharedMemorySize, rec_smem);
    rnn_persist<<<dim3(NJT, NG), 256, rec_smem>>>(X, state, W_xh, W_hh, b_h);

    // 2) bulk-pipelined tensor-core projection GEMM
    cudaFuncSetAttribute(proj_bulk, cudaFuncAttributeMaxDynamicSharedMemorySize, PROJ_SMEM);
    proj_bulk<<<dim3(VOCAB / PN, M_TOT / PM), 512, PROJ_SMEM>>>(b_q, out);

    // 3) optional H_final tail
    if (out_size >= M_TOT * VOCAB + B * HID) {
        copy_hfinal<<<(B * HID + 255) / 256, 256>>>(out + (size_t)M_TOT * VOCAB);
    }
}